// round 5
// baseline (speedup 1.0000x reference)
#include <cuda_runtime.h>
#include <cstdint>
#include <math.h>

// ============================================================================
// Problem constants
// ============================================================================
#define N_ROWS   30000
#define D_IN     784
#define N_CLS    10
#define NC       100     // candidates per iteration (2 lambdas * 50)
#define MAXK     12
#define INITB    4000
#define BINC     2166
#define NBUCK    4096    // 12-bit bucketing for the stable sort

// ============================================================================
// Device globals (scratch; no allocations allowed)
// ============================================================================
__device__ uint2 dk_key;          // PRNG chain key
__device__ uint2 dk_w, dk_b;      // per-iter subkeys for W_random / b_random
__device__ uint2 dk_sk[2];        // per-iter sort subkeys (2 shuffle rounds)

__device__ unsigned long long d_pack[N_ROWS];
__device__ unsigned long long d_pack2[N_ROWS];
__device__ unsigned int d_hist[NBUCK];
__device__ unsigned int d_offs[NBUCK];
__device__ unsigned int d_woffs[NBUCK];
__device__ int d_perm[N_ROWS];

__device__ float d_Wr[D_IN * NC];
__device__ float d_br[NC];
__device__ float d_y[N_ROWS * N_CLS];
__device__ float d_H[N_ROWS * MAXK];
__device__ float d_part[436 * 1104];     // per-block GEMM partials (max 435 blocks)
__device__ int   d_best;
__device__ double d_gpart[120 * 264];
__device__ double d_G[144];
__device__ double d_C[120];
__device__ float d_beta[MAXK * N_CLS];

// ============================================================================
// JAX Threefry-2x32 core (bit-exact)
// ============================================================================
__device__ __forceinline__ uint32_t rotl32(uint32_t x, int r) {
    return (x << r) | (x >> (32 - r));
}

__device__ __forceinline__ void tf2x32(uint32_t k0, uint32_t k1,
                                       uint32_t x0, uint32_t x1,
                                       uint32_t& o0, uint32_t& o1) {
    uint32_t ks2 = k0 ^ k1 ^ 0x1BD11BDAu;
    x0 += k0; x1 += k1;
#define TFR(r) { x0 += x1; x1 = rotl32(x1, r); x1 ^= x0; }
    TFR(13) TFR(15) TFR(26) TFR(6)   x0 += k1;  x1 += ks2 + 1u;
    TFR(17) TFR(29) TFR(16) TFR(24)  x0 += ks2; x1 += k0  + 2u;
    TFR(13) TFR(15) TFR(26) TFR(6)   x0 += k0;  x1 += k1  + 3u;
    TFR(17) TFR(29) TFR(16) TFR(24)  x0 += k1;  x1 += ks2 + 4u;
    TFR(13) TFR(15) TFR(26) TFR(6)   x0 += ks2; x1 += k0  + 5u;
#undef TFR
    o0 = x0; o1 = x1;
}

// ---- threefry_partitionable=True semantics (JAX >= 0.4.36 default) ----
// random_bits(key, 32, shape) element i (flat, row-major; hi-32 of i64 index = 0):
//   (o0, o1) = threefry2x32(key, (0, i)); bits = o0 ^ o1
__device__ __forceinline__ uint32_t rbits(uint2 key, uint32_t i) {
    uint32_t o0, o1;
    tf2x32(key.x, key.y, 0u, i, o0, o1);
    return o0 ^ o1;
}

// split(key, n)[j] (fold-like): subkey = threefry2x32(key, (0, j)) as (o0, o1)
__device__ __forceinline__ uint2 subkey(uint2 key, uint32_t j) {
    uint2 r;
    tf2x32(key.x, key.y, 0u, j, r.x, r.y);
    return r;
}

__device__ __forceinline__ float uni01(uint32_t bits) {
    return __uint_as_float((bits >> 9) | 0x3f800000u) - 1.0f;
}

// ============================================================================
// Kernels
// ============================================================================
__global__ void k_init() {
    if (threadIdx.x == 0) { dk_key = make_uint2(0u, 42u); }  // jax.random.key(42)
}

__global__ void k_zeroy() {
    int t = blockIdx.x * blockDim.x + threadIdx.x;
    if (t < N_ROWS * N_CLS) d_y[t] = 0.0f;
}

// Per-iteration key derivation: key,kperm,kw,kb = split(key,4); shuffle subkeys.
__global__ void k_keys() {
    if (threadIdx.x != 0) return;
    uint2 key   = dk_key;
    uint2 nk    = subkey(key, 0);
    uint2 kperm = subkey(key, 1);
    dk_w        = subkey(key, 2);
    dk_b        = subkey(key, 3);
    dk_key = nk;
    // _shuffle: (key1, sk1) = split(kperm); (key2, sk2) = split(key1)
    uint2 kp1 = subkey(kperm, 0);
    dk_sk[0]  = subkey(kperm, 1);
    dk_sk[1]  = subkey(kp1,   1);
}

__global__ void k_zerohist() {
    int t = blockIdx.x * blockDim.x + threadIdx.x;
    if (t < NBUCK) d_hist[t] = 0u;
}

// Generate sort keys + pack (key:32 | pos:15 | val:15) + histogram top-12-bits.
__global__ void k_genhist(int round) {
    int i = blockIdx.x * blockDim.x + threadIdx.x;
    if (i >= N_ROWS) return;
    uint32_t key = rbits(dk_sk[round], (uint32_t)i);
    uint32_t val = (round == 0) ? (uint32_t)i : (uint32_t)d_perm[i];
    unsigned long long p = ((unsigned long long)key << 30) |
                           ((unsigned long long)(uint32_t)i << 15) |
                           (unsigned long long)val;
    d_pack[i] = p;
    atomicAdd(&d_hist[key >> 20], 1u);
}

// Exclusive scan of 4096 histogram bins (one block, 1024 threads).
__global__ void k_scan() {
    __shared__ unsigned int h[NBUCK];
    __shared__ unsigned int ps[1024];
    int t = threadIdx.x;
    for (int i = t; i < NBUCK; i += 1024) h[i] = d_hist[i];
    __syncthreads();
    unsigned int s = 0;
    for (int j = 0; j < 4; j++) s += h[t * 4 + j];
    ps[t] = s;
    __syncthreads();
    for (int off = 1; off < 1024; off <<= 1) {
        unsigned int v = (t >= off) ? ps[t - off] : 0u;
        __syncthreads();
        ps[t] += v;
        __syncthreads();
    }
    unsigned int base = (t > 0) ? ps[t - 1] : 0u;
    for (int j = 0; j < 4; j++) {
        d_offs[t * 4 + j]  = base;
        d_woffs[t * 4 + j] = base;
        base += h[t * 4 + j];
    }
}

__global__ void k_scatter() {
    int i = blockIdx.x * blockDim.x + threadIdx.x;
    if (i >= N_ROWS) return;
    unsigned long long p = d_pack[i];
    unsigned int b = (unsigned int)(p >> 50);
    unsigned int pos = atomicAdd(&d_woffs[b], 1u);
    d_pack2[pos] = p;
}

// Per-bucket insertion sort on the full 62-bit composite => globally stable order.
__global__ void k_bsort() {
    int b = blockIdx.x * blockDim.x + threadIdx.x;
    if (b >= NBUCK) return;
    unsigned int start = d_offs[b];
    unsigned int cnt = d_hist[b];
    if (cnt > 64u) cnt = 64u;   // Poisson(7.3): P(>64) ~ 1e-30
    unsigned long long a[64];
    for (unsigned int i = 0; i < cnt; i++) a[i] = d_pack2[start + i];
    for (unsigned int i = 1; i < cnt; i++) {
        unsigned long long key = a[i];
        int j = (int)i - 1;
        while (j >= 0 && a[j] > key) { a[j + 1] = a[j]; j--; }
        a[j + 1] = key;
    }
    for (unsigned int i = 0; i < cnt; i++)
        d_perm[start + i] = (int)(a[i] & 0x7FFFull);
}

// W_random (784x100) and b_random (100) via jax.random.uniform, scaled by lambda.
__global__ void k_genc() {
    int i = blockIdx.x * blockDim.x + threadIdx.x;
    if (i < D_IN * NC) {
        float u = uni01(rbits(dk_w, (uint32_t)i));
        int col = i % NC;
        float lam = (col < 50) ? 1.0f : 10.0f;
        d_Wr[i] = lam * (2.0f * u - 1.0f);
    } else if (i < D_IN * NC + NC) {
        int j = i - D_IN * NC;
        float u = uni01(rbits(dk_b, (uint32_t)j));
        float lam = (j < 50) ? 1.0f : 10.0f;
        d_br[j] = lam * (2.0f * u - 1.0f);
    }
}

// Fused: h = sigmoid(X[idx] @ Wr + br) for a 64-row tile x all 100 candidates,
// plus deterministic in-block reduction of ek^T h and sum(h^2).
#define BM 64
#define KT 28
__global__ void __launch_bounds__(400)
k_cand(const float* __restrict__ X, const float* __restrict__ Y, int batch) {
    __shared__ float As[BM * KT];
    __shared__ float Bs[KT * NC];
    __shared__ float ekS[BM * N_CLS];
    __shared__ int idxS[BM];
    __shared__ float red[4 * NC * 11];

    int c = threadIdx.x;              // 0..99 candidate
    int ry = threadIdx.y;             // 0..3
    int tid = ry * NC + c;            // 0..399
    int row0 = blockIdx.x * BM;

    for (int t = tid; t < BM; t += 400) {
        int g = row0 + t;
        idxS[t] = (g < batch) ? d_perm[g] : -1;
    }
    __syncthreads();
    for (int t = tid; t < BM * N_CLS; t += 400) {
        int r = t / N_CLS, j = t % N_CLS;
        int idx = idxS[r];
        ekS[t] = (idx >= 0) ? (Y[idx * N_CLS + j] - d_y[idx * N_CLS + j]) : 0.0f;
    }

    float acc[16];
#pragma unroll
    for (int r = 0; r < 16; r++) acc[r] = 0.0f;

    for (int k0 = 0; k0 < D_IN; k0 += KT) {
        __syncthreads();
        for (int t = tid; t < BM * KT; t += 400) {
            int r = t / KT, q = t % KT;
            int idx = idxS[r];
            As[t] = (idx >= 0) ? X[idx * D_IN + k0 + q] : 0.0f;
        }
        for (int t = tid; t < KT * NC; t += 400) {
            Bs[t] = d_Wr[k0 * NC + t];
        }
        __syncthreads();
#pragma unroll
        for (int q = 0; q < KT; q++) {
            float b = Bs[q * NC + c];
#pragma unroll
            for (int r = 0; r < 16; r++) {
                acc[r] += As[(ry + 4 * r) * KT + q] * b;
            }
        }
    }
    float bias = d_br[c];
    float m[N_CLS];
    float s2 = 0.0f;
#pragma unroll
    for (int j = 0; j < N_CLS; j++) m[j] = 0.0f;
#pragma unroll
    for (int r = 0; r < 16; r++) {
        int rr = ry + 4 * r;
        if (idxS[rr] >= 0) {
            float h = 1.0f / (1.0f + expf(-(acc[r] + bias)));
            s2 += h * h;
#pragma unroll
            for (int j = 0; j < N_CLS; j++) m[j] += ekS[rr * N_CLS + j] * h;
        }
    }
    float* myred = &red[(ry * NC + c) * 11];
#pragma unroll
    for (int j = 0; j < N_CLS; j++) myred[j] = m[j];
    myred[10] = s2;
    __syncthreads();
    if (ry == 0) {
        for (int q = 0; q < 11; q++) {
            float s = red[(0 * NC + c) * 11 + q] + red[(1 * NC + c) * 11 + q] +
                      red[(2 * NC + c) * 11 + q] + red[(3 * NC + c) * 11 + q];
            d_part[blockIdx.x * 1104 + c * 11 + q] = s;
        }
    }
}

// Deterministic final reduce of partials + v computation + argmax.
__global__ void k_vred(int nb) {
    __shared__ float v[NC];
    int c = threadIdx.x;
    if (c < NC) {
        double m[N_CLS];
        double s2 = 0.0;
        for (int j = 0; j < N_CLS; j++) m[j] = 0.0;
        for (int b = 0; b < nb; b++) {
            const float* p = &d_part[b * 1104 + c * 11];
            for (int j = 0; j < N_CLS; j++) m[j] += (double)p[j];
            s2 += (double)p[10];
        }
        double num = 0.0;
        for (int j = 0; j < N_CLS; j++) num += m[j] * m[j];
        v[c] = (float)(num / (10.0 * s2));
    }
    __syncthreads();
    if (c == 0) {
        float best = -1.0f;
        int bi = 0;
        for (int i = 0; i < NC; i++)
            if (v[i] > best) { best = v[i]; bi = i; }
        d_best = bi;
    }
}

// h_c = sigmoid(X @ W_best + b_best) over all rows; also emits W,b outputs.
__global__ void k_hc(const float* __restrict__ X, float* __restrict__ out, int k) {
    __shared__ float Wc[D_IN];
    __shared__ float s_b;
    int best = d_best;
    for (int t = threadIdx.x; t < D_IN; t += 256) Wc[t] = d_Wr[t * NC + best];
    if (threadIdx.x == 0) s_b = d_br[best];
    __syncthreads();
    int w = threadIdx.x >> 5, lane = threadIdx.x & 31;
    int row = blockIdx.x * 8 + w;
    if (row < N_ROWS) {
        const float* xr = X + row * D_IN;
        float s = 0.0f;
        for (int q = lane; q < D_IN; q += 32) s += xr[q] * Wc[q];
#pragma unroll
        for (int o = 16; o; o >>= 1) s += __shfl_down_sync(0xffffffffu, s, o);
        if (lane == 0) {
            float h = 1.0f / (1.0f + expf(-(s + s_b)));
            d_H[row * MAXK + k] = h;
        }
    }
    if (blockIdx.x == 0) {
        for (int t = threadIdx.x; t < D_IN; t += 256) out[t * MAXK + k] = Wc[t];
        if (threadIdx.x == 0) out[D_IN * MAXK + k] = s_b;
    }
}

// fp64 Gram partials: per-block accumulation of H^T H and H^T Y.
#define GB 120
__global__ void k_gram(const float* __restrict__ Y, int n) {
    __shared__ float sH[64 * MAXK];
    __shared__ float sY[64 * N_CLS];
    int e = threadIdx.x;  // blockDim = 264
    int nent = n * n + n * N_CLS;
    double acc = 0.0;
    int r0 = blockIdx.x * (N_ROWS / GB);
    int r1 = r0 + (N_ROWS / GB);
    for (int rb = r0; rb < r1; rb += 64) {
        int cnt = min(64, r1 - rb);
        __syncthreads();
        for (int t = e; t < cnt * MAXK; t += 264)
            sH[t] = d_H[(rb + t / MAXK) * MAXK + t % MAXK];
        for (int t = e; t < cnt * N_CLS; t += 264)
            sY[t] = Y[(rb + t / N_CLS) * N_CLS + t % N_CLS];
        __syncthreads();
        if (e < nent) {
            if (e < n * n) {
                int a = e / n, b = e % n;
                for (int r = 0; r < cnt; r++)
                    acc += (double)sH[r * MAXK + a] * (double)sH[r * MAXK + b];
            } else {
                int e2 = e - n * n;
                int a = e2 / N_CLS, j = e2 % N_CLS;
                for (int r = 0; r < cnt; r++)
                    acc += (double)sH[r * MAXK + a] * (double)sY[r * N_CLS + j];
            }
        }
    }
    d_gpart[blockIdx.x * 264 + e] = acc;
}

__global__ void k_gred(int n) {
    int e = threadIdx.x;
    if (e >= 264) return;
    double s = 0.0;
    for (int b = 0; b < GB; b++) s += d_gpart[b * 264 + e];
    if (e < n * n) {
        d_G[(e / n) * MAXK + (e % n)] = s;
    } else if (e < n * n + n * N_CLS) {
        int e2 = e - n * n;
        d_C[(e2 / N_CLS) * N_CLS + e2 % N_CLS] = s;
    }
}

// fp64 Cholesky solve of (H^T H) beta = H^T Y (n <= 12, 10 RHS).
__global__ void k_solve(float* __restrict__ out, int n) {
    __shared__ double L[144], Bm[120];
    int t = threadIdx.x;
    if (t == 0) {
        for (int a = 0; a < n; a++)
            for (int b = 0; b < n; b++) L[a * 12 + b] = d_G[a * 12 + b];
        for (int a = 0; a < n; a++)
            for (int j = 0; j < N_CLS; j++) Bm[a * 10 + j] = d_C[a * 10 + j];
        for (int j = 0; j < n; j++) {
            double s = L[j * 12 + j];
            for (int p = 0; p < j; p++) s -= L[j * 12 + p] * L[j * 12 + p];
            double dg = sqrt(s);
            L[j * 12 + j] = dg;
            for (int i = j + 1; i < n; i++) {
                double s2 = L[i * 12 + j];
                for (int p = 0; p < j; p++) s2 -= L[i * 12 + p] * L[j * 12 + p];
                L[i * 12 + j] = s2 / dg;
            }
        }
    }
    __syncthreads();
    if (t < N_CLS) {
        double z[12];
        for (int i = 0; i < n; i++) {
            double s = Bm[i * 10 + t];
            for (int p = 0; p < i; p++) s -= L[i * 12 + p] * z[p];
            z[i] = s / L[i * 12 + i];
        }
        for (int i = n - 1; i >= 0; i--) {
            double s = z[i];
            for (int p = i + 1; p < n; p++) s -= L[p * 12 + i] * z[p];
            z[i] = s / L[i * 12 + i];
        }
        for (int i = 0; i < n; i++) {
            d_beta[i * 10 + t] = (float)z[i];
            if (n == MAXK) out[D_IN * MAXK + MAXK + i * 10 + t] = (float)z[i];
        }
    }
}

// y = H[:, :n] @ beta
__global__ void k_yupd(int n) {
    int t = blockIdx.x * blockDim.x + threadIdx.x;
    if (t >= N_ROWS * N_CLS) return;
    int i = t / N_CLS, j = t % N_CLS;
    float s = 0.0f;
    for (int q = 0; q < n; q++) s += d_H[i * MAXK + q] * d_beta[q * 10 + j];
    d_y[t] = s;
}

// ============================================================================
// Launch
// ============================================================================
extern "C" void kernel_launch(void* const* d_in, const int* in_sizes, int n_in,
                              void* d_out, int out_size) {
    const float* X = (const float*)d_in[0];
    const float* Y = (const float*)d_in[1];
    float* out = (float*)d_out;

    k_init<<<1, 32>>>();
    k_zeroy<<<(N_ROWS * N_CLS + 255) / 256, 256>>>();

    int batch = INITB;
    for (int k = 0; k < MAXK; k++) {
        k_keys<<<1, 32>>>();
        for (int r = 0; r < 2; r++) {
            k_zerohist<<<NBUCK / 256, 256>>>();
            k_genhist<<<(N_ROWS + 255) / 256, 256>>>(r);
            k_scan<<<1, 1024>>>();
            k_scatter<<<(N_ROWS + 255) / 256, 256>>>();
            k_bsort<<<NBUCK / 128, 128>>>();
        }
        k_genc<<<(D_IN * NC + NC + 255) / 256, 256>>>();

        int nb = (batch + BM - 1) / BM;
        dim3 cb(NC, 4);
        k_cand<<<nb, cb>>>(X, Y, batch);
        k_vred<<<1, 128>>>(nb);
        k_hc<<<(N_ROWS + 7) / 8, 256>>>(X, out, k);
        k_gram<<<GB, 264>>>(Y, k + 1);
        k_gred<<<1, 288>>>(k + 1);
        k_solve<<<1, 32>>>(out, k + 1);
        k_yupd<<<(N_ROWS * N_CLS + 255) / 256, 256>>>(k + 1);

        batch += BINC;
    }
}

// round 6
// speedup vs baseline: 1.5427x; 1.5427x over previous
#include <cuda_runtime.h>
#include <cstdint>
#include <math.h>

// ============================================================================
// Problem constants
// ============================================================================
#define N_ROWS   30000
#define D_IN     784
#define N_CLS    10
#define NC       100     // candidates per iteration (2 lambdas * 50)
#define MAXK     12
#define INITB    4000
#define BINC     2166
#define NBUCK    4096    // 12-bit bucketing for the stable sort

// ============================================================================
// Device globals (scratch; no allocations allowed)
// ============================================================================
__device__ uint2 dk_key;          // PRNG chain key
__device__ uint2 dk_w, dk_b;      // per-iter subkeys for W_random / b_random
__device__ uint2 dk_sk[2];        // per-iter sort subkeys (2 shuffle rounds)

__device__ unsigned long long d_pack[N_ROWS];
__device__ unsigned long long d_pack2[N_ROWS];
__device__ unsigned int d_hist[NBUCK];
__device__ unsigned int d_offs[NBUCK];
__device__ unsigned int d_woffs[NBUCK];
__device__ int d_perm[N_ROWS];

__device__ float d_Wr[D_IN * NC];
__device__ float d_br[NC];
__device__ float d_y[N_ROWS * N_CLS];
__device__ float d_H[N_ROWS * MAXK];
__device__ float d_part[436 * 1104];     // per-block GEMM partials (max 435 blocks)
__device__ int   d_best;
__device__ double d_gpart[120 * 264];
__device__ double d_G[144];
__device__ double d_C[120];
__device__ float d_beta[MAXK * N_CLS];

// ============================================================================
// JAX Threefry-2x32 core (bit-exact)
// ============================================================================
__device__ __forceinline__ uint32_t rotl32(uint32_t x, int r) {
    return (x << r) | (x >> (32 - r));
}

__device__ __forceinline__ void tf2x32(uint32_t k0, uint32_t k1,
                                       uint32_t x0, uint32_t x1,
                                       uint32_t& o0, uint32_t& o1) {
    uint32_t ks2 = k0 ^ k1 ^ 0x1BD11BDAu;
    x0 += k0; x1 += k1;
#define TFR(r) { x0 += x1; x1 = rotl32(x1, r); x1 ^= x0; }
    TFR(13) TFR(15) TFR(26) TFR(6)   x0 += k1;  x1 += ks2 + 1u;
    TFR(17) TFR(29) TFR(16) TFR(24)  x0 += ks2; x1 += k0  + 2u;
    TFR(13) TFR(15) TFR(26) TFR(6)   x0 += k0;  x1 += k1  + 3u;
    TFR(17) TFR(29) TFR(16) TFR(24)  x0 += k1;  x1 += ks2 + 4u;
    TFR(13) TFR(15) TFR(26) TFR(6)   x0 += ks2; x1 += k0  + 5u;
#undef TFR
    o0 = x0; o1 = x1;
}

// ---- threefry_partitionable=True semantics (JAX >= 0.4.36 default) ----
__device__ __forceinline__ uint32_t rbits(uint2 key, uint32_t i) {
    uint32_t o0, o1;
    tf2x32(key.x, key.y, 0u, i, o0, o1);
    return o0 ^ o1;
}

__device__ __forceinline__ uint2 subkey(uint2 key, uint32_t j) {
    uint2 r;
    tf2x32(key.x, key.y, 0u, j, r.x, r.y);
    return r;
}

__device__ __forceinline__ float uni01(uint32_t bits) {
    return __uint_as_float((bits >> 9) | 0x3f800000u) - 1.0f;
}

// ============================================================================
// Small kernels (PRNG / permutation)
// ============================================================================
__global__ void k_init() {
    if (threadIdx.x == 0) { dk_key = make_uint2(0u, 42u); }  // jax.random.key(42)
}

__global__ void k_zeroy() {
    int t = blockIdx.x * blockDim.x + threadIdx.x;
    if (t < N_ROWS * N_CLS) d_y[t] = 0.0f;
}

__global__ void k_keys() {
    if (threadIdx.x != 0) return;
    uint2 key   = dk_key;
    uint2 nk    = subkey(key, 0);
    uint2 kperm = subkey(key, 1);
    dk_w        = subkey(key, 2);
    dk_b        = subkey(key, 3);
    dk_key = nk;
    uint2 kp1 = subkey(kperm, 0);
    dk_sk[0]  = subkey(kperm, 1);
    dk_sk[1]  = subkey(kp1,   1);
}

__global__ void k_zerohist() {
    int t = blockIdx.x * blockDim.x + threadIdx.x;
    if (t < NBUCK) d_hist[t] = 0u;
}

__global__ void k_genhist(int round) {
    int i = blockIdx.x * blockDim.x + threadIdx.x;
    if (i >= N_ROWS) return;
    uint32_t key = rbits(dk_sk[round], (uint32_t)i);
    uint32_t val = (round == 0) ? (uint32_t)i : (uint32_t)d_perm[i];
    unsigned long long p = ((unsigned long long)key << 30) |
                           ((unsigned long long)(uint32_t)i << 15) |
                           (unsigned long long)val;
    d_pack[i] = p;
    atomicAdd(&d_hist[key >> 20], 1u);
}

__global__ void k_scan() {
    __shared__ unsigned int h[NBUCK];
    __shared__ unsigned int ps[1024];
    int t = threadIdx.x;
    for (int i = t; i < NBUCK; i += 1024) h[i] = d_hist[i];
    __syncthreads();
    unsigned int s = 0;
    for (int j = 0; j < 4; j++) s += h[t * 4 + j];
    ps[t] = s;
    __syncthreads();
    for (int off = 1; off < 1024; off <<= 1) {
        unsigned int v = (t >= off) ? ps[t - off] : 0u;
        __syncthreads();
        ps[t] += v;
        __syncthreads();
    }
    unsigned int base = (t > 0) ? ps[t - 1] : 0u;
    for (int j = 0; j < 4; j++) {
        d_offs[t * 4 + j]  = base;
        d_woffs[t * 4 + j] = base;
        base += h[t * 4 + j];
    }
}

__global__ void k_scatter() {
    int i = blockIdx.x * blockDim.x + threadIdx.x;
    if (i >= N_ROWS) return;
    unsigned long long p = d_pack[i];
    unsigned int b = (unsigned int)(p >> 50);
    unsigned int pos = atomicAdd(&d_woffs[b], 1u);
    d_pack2[pos] = p;
}

__global__ void k_bsort() {
    int b = blockIdx.x * blockDim.x + threadIdx.x;
    if (b >= NBUCK) return;
    unsigned int start = d_offs[b];
    unsigned int cnt = d_hist[b];
    if (cnt > 64u) cnt = 64u;
    unsigned long long a[64];
    for (unsigned int i = 0; i < cnt; i++) a[i] = d_pack2[start + i];
    for (unsigned int i = 1; i < cnt; i++) {
        unsigned long long key = a[i];
        int j = (int)i - 1;
        while (j >= 0 && a[j] > key) { a[j + 1] = a[j]; j--; }
        a[j + 1] = key;
    }
    for (unsigned int i = 0; i < cnt; i++)
        d_perm[start + i] = (int)(a[i] & 0x7FFFull);
}

__global__ void k_genc() {
    int i = blockIdx.x * blockDim.x + threadIdx.x;
    if (i < D_IN * NC) {
        float u = uni01(rbits(dk_w, (uint32_t)i));
        int col = i % NC;
        float lam = (col < 50) ? 1.0f : 10.0f;
        d_Wr[i] = lam * (2.0f * u - 1.0f);
    } else if (i < D_IN * NC + NC) {
        int j = i - D_IN * NC;
        float u = uni01(rbits(dk_b, (uint32_t)j));
        float lam = (j < 50) ? 1.0f : 10.0f;
        d_br[j] = lam * (2.0f * u - 1.0f);
    }
}

// ============================================================================
// Candidate evaluation: register-tiled gather-GEMM + shfl-reduced scores.
//
// Block: 64 rows x 100 candidates. 400 threads: tx = tid/16 (candidate group
// of 4), ty = tid%16 (row group of 4). Per k-step: 2x LDS.128 + 16 FFMA.
// Epilogue: sigmoid, then ek^T h and sum(h^2) reduced across the 16 row
// threads (consecutive lanes) via shfl_xor -> deterministic block partials.
// ============================================================================
#define BM 64
#define KT 56
#define NTILE (D_IN / KT)   // 14

__global__ void __launch_bounds__(400, 3)
k_cand(const float* __restrict__ X, const float* __restrict__ Y, int batch) {
    __shared__ float As[KT][68];       // transposed A tile (pad 68 floats/row)
    __shared__ float Bs[KT][NC];       // W tile, same layout as d_Wr slice
    __shared__ float ekS[BM][N_CLS];
    __shared__ int idxS[BM];

    int tid = threadIdx.x;
    int tx = tid >> 4;                 // 0..24 candidate group
    int ty = tid & 15;                 // 0..15 row group
    int row0 = blockIdx.x * BM;

    if (tid < BM) {
        int g = row0 + tid;
        idxS[tid] = (g < batch) ? d_perm[g] : -1;
    }
    __syncthreads();
    for (int t = tid; t < BM * N_CLS; t += 400) {
        int r = t / N_CLS, j = t % N_CLS;
        int idx = idxS[r];
        ekS[r][j] = (idx >= 0) ? (Y[idx * N_CLS + j] - d_y[idx * N_CLS + j]) : 0.0f;
    }

    float acc[16];
#pragma unroll
    for (int i = 0; i < 16; i++) acc[i] = 0.0f;

    for (int t14 = 0; t14 < NTILE; t14++) {
        int k0 = t14 * KT;
        __syncthreads();
        // A tile: 64 rows x 56 k, transposed into As[k][r]
        for (int e = tid; e < BM * (KT / 4); e += 400) {
            int r = e / (KT / 4);
            int v = e % (KT / 4);
            int idx = idxS[r];
            float4 x = make_float4(0.f, 0.f, 0.f, 0.f);
            if (idx >= 0)
                x = *reinterpret_cast<const float4*>(X + (size_t)idx * D_IN + k0 + v * 4);
            As[v * 4 + 0][r] = x.x;
            As[v * 4 + 1][r] = x.y;
            As[v * 4 + 2][r] = x.z;
            As[v * 4 + 3][r] = x.w;
        }
        // B tile: flat float4 copy of d_Wr[k0*NC .. k0*NC + KT*NC)
        {
            const float4* src = reinterpret_cast<const float4*>(d_Wr + k0 * NC);
            float4* dst = reinterpret_cast<float4*>(&Bs[0][0]);
            for (int e = tid; e < KT * NC / 4; e += 400) dst[e] = src[e];
        }
        __syncthreads();
#pragma unroll 8
        for (int q = 0; q < KT; q++) {
            float4 a = *reinterpret_cast<const float4*>(&As[q][ty * 4]);
            float4 b = *reinterpret_cast<const float4*>(&Bs[q][tx * 4]);
            acc[0]  += a.x * b.x;  acc[1]  += a.x * b.y;
            acc[2]  += a.x * b.z;  acc[3]  += a.x * b.w;
            acc[4]  += a.y * b.x;  acc[5]  += a.y * b.y;
            acc[6]  += a.y * b.z;  acc[7]  += a.y * b.w;
            acc[8]  += a.z * b.x;  acc[9]  += a.z * b.y;
            acc[10] += a.z * b.z;  acc[11] += a.z * b.w;
            acc[12] += a.w * b.x;  acc[13] += a.w * b.y;
            acc[14] += a.w * b.z;  acc[15] += a.w * b.w;
        }
    }

    // Epilogue: h = sigmoid(acc + bias), masked to valid rows.
    float bj[4];
#pragma unroll
    for (int j = 0; j < 4; j++) bj[j] = d_br[tx * 4 + j];
    bool vld[4];
#pragma unroll
    for (int i = 0; i < 4; i++) vld[i] = (idxS[ty * 4 + i] >= 0);

    float h[16];
#pragma unroll
    for (int i = 0; i < 4; i++) {
#pragma unroll
        for (int j = 0; j < 4; j++) {
            float z = acc[i * 4 + j] + bj[j];
            h[i * 4 + j] = vld[i] ? (1.0f / (1.0f + expf(-z))) : 0.0f;
        }
    }

    int pbase = blockIdx.x * 1104 + (tx * 4) * 11;

    // s2 per candidate
#pragma unroll
    for (int j = 0; j < 4; j++) {
        float s2 = h[j] * h[j] + h[4 + j] * h[4 + j] +
                   h[8 + j] * h[8 + j] + h[12 + j] * h[12 + j];
#pragma unroll
        for (int o = 1; o < 16; o <<= 1) s2 += __shfl_xor_sync(0xffffffffu, s2, o);
        if (ty == 0) d_part[pbase + j * 11 + 10] = s2;
    }
    // m[j] = ek(:,jc)^T h(:,j) per class jc
#pragma unroll
    for (int jc = 0; jc < N_CLS; jc++) {
        float e0 = ekS[ty * 4 + 0][jc];
        float e1 = ekS[ty * 4 + 1][jc];
        float e2 = ekS[ty * 4 + 2][jc];
        float e3 = ekS[ty * 4 + 3][jc];
#pragma unroll
        for (int j = 0; j < 4; j++) {
            float m = e0 * h[j] + e1 * h[4 + j] + e2 * h[8 + j] + e3 * h[12 + j];
#pragma unroll
            for (int o = 1; o < 16; o <<= 1) m += __shfl_xor_sync(0xffffffffu, m, o);
            if (ty == 0) d_part[pbase + j * 11 + jc] = m;
        }
    }
}

// Deterministic final reduce of partials + v computation + argmax (4-way split).
__global__ void k_vred(int nb) {
    __shared__ float v[NC];
    int tid = threadIdx.x;          // 400
    int c = tid >> 2, p = tid & 3;
    double m[N_CLS];
    double s2 = 0.0;
    for (int j = 0; j < N_CLS; j++) m[j] = 0.0;
    for (int b = p; b < nb; b += 4) {
        const float* pp = &d_part[b * 1104 + c * 11];
        for (int j = 0; j < N_CLS; j++) m[j] += (double)pp[j];
        s2 += (double)pp[10];
    }
    // combine the 4 strided partials (p = low 2 lane bits) via xor-shfl: fixed association
    for (int j = 0; j < N_CLS; j++) {
        m[j] += __shfl_xor_sync(0xffffffffu, m[j], 1);
        m[j] += __shfl_xor_sync(0xffffffffu, m[j], 2);
    }
    s2 += __shfl_xor_sync(0xffffffffu, s2, 1);
    s2 += __shfl_xor_sync(0xffffffffu, s2, 2);
    if (p == 0) {
        double num = 0.0;
        for (int j = 0; j < N_CLS; j++) num += m[j] * m[j];
        v[c] = (float)(num / (10.0 * s2));
    }
    __syncthreads();
    if (tid == 0) {
        float best = -1.0f;
        int bi = 0;
        for (int i = 0; i < NC; i++)
            if (v[i] > best) { best = v[i]; bi = i; }
        d_best = bi;
    }
}

// h_c = sigmoid(X @ W_best + b_best) over all rows; also emits W,b outputs.
__global__ void k_hc(const float* __restrict__ X, float* __restrict__ out, int k) {
    __shared__ float Wc[D_IN];
    __shared__ float s_b;
    int best = d_best;
    for (int t = threadIdx.x; t < D_IN; t += 256) Wc[t] = d_Wr[t * NC + best];
    if (threadIdx.x == 0) s_b = d_br[best];
    __syncthreads();
    int w = threadIdx.x >> 5, lane = threadIdx.x & 31;
    int row = blockIdx.x * 8 + w;
    if (row < N_ROWS) {
        const float* xr = X + (size_t)row * D_IN;
        float s = 0.0f;
        for (int q = lane; q < D_IN; q += 32) s += xr[q] * Wc[q];
#pragma unroll
        for (int o = 16; o; o >>= 1) s += __shfl_down_sync(0xffffffffu, s, o);
        if (lane == 0) {
            float h = 1.0f / (1.0f + expf(-(s + s_b)));
            d_H[row * MAXK + k] = h;
        }
    }
    if (blockIdx.x == 0) {
        for (int t = threadIdx.x; t < D_IN; t += 256) out[t * MAXK + k] = Wc[t];
        if (threadIdx.x == 0) out[D_IN * MAXK + k] = s_b;
    }
}

// fp64 Gram partials: per-block accumulation of H^T H and H^T Y.
#define GB 120
__global__ void k_gram(const float* __restrict__ Y, int n) {
    __shared__ float sH[64 * MAXK];
    __shared__ float sY[64 * N_CLS];
    int e = threadIdx.x;  // blockDim = 264
    int nent = n * n + n * N_CLS;
    double acc = 0.0;
    int r0 = blockIdx.x * (N_ROWS / GB);
    int r1 = r0 + (N_ROWS / GB);
    for (int rb = r0; rb < r1; rb += 64) {
        int cnt = min(64, r1 - rb);
        __syncthreads();
        for (int t = e; t < cnt * MAXK; t += 264)
            sH[t] = d_H[(rb + t / MAXK) * MAXK + t % MAXK];
        for (int t = e; t < cnt * N_CLS; t += 264)
            sY[t] = Y[(rb + t / N_CLS) * N_CLS + t % N_CLS];
        __syncthreads();
        if (e < nent) {
            if (e < n * n) {
                int a = e / n, b = e % n;
                for (int r = 0; r < cnt; r++)
                    acc += (double)sH[r * MAXK + a] * (double)sH[r * MAXK + b];
            } else {
                int e2 = e - n * n;
                int a = e2 / N_CLS, j = e2 % N_CLS;
                for (int r = 0; r < cnt; r++)
                    acc += (double)sH[r * MAXK + a] * (double)sY[r * N_CLS + j];
            }
        }
    }
    d_gpart[blockIdx.x * 264 + e] = acc;
}

__global__ void k_gred(int n) {
    int e = threadIdx.x;
    if (e >= 264) return;
    double s = 0.0;
    for (int b = 0; b < GB; b++) s += d_gpart[b * 264 + e];
    if (e < n * n) {
        d_G[(e / n) * MAXK + (e % n)] = s;
    } else if (e < n * n + n * N_CLS) {
        int e2 = e - n * n;
        d_C[(e2 / N_CLS) * N_CLS + e2 % N_CLS] = s;
    }
}

// fp64 Cholesky solve of (H^T H) beta = H^T Y (n <= 12, 10 RHS).
__global__ void k_solve(float* __restrict__ out, int n) {
    __shared__ double L[144], Bm[120];
    int t = threadIdx.x;
    if (t == 0) {
        for (int a = 0; a < n; a++)
            for (int b = 0; b < n; b++) L[a * 12 + b] = d_G[a * 12 + b];
        for (int a = 0; a < n; a++)
            for (int j = 0; j < N_CLS; j++) Bm[a * 10 + j] = d_C[a * 10 + j];
        for (int j = 0; j < n; j++) {
            double s = L[j * 12 + j];
            for (int p = 0; p < j; p++) s -= L[j * 12 + p] * L[j * 12 + p];
            double dg = sqrt(s);
            L[j * 12 + j] = dg;
            for (int i = j + 1; i < n; i++) {
                double s2 = L[i * 12 + j];
                for (int p = 0; p < j; p++) s2 -= L[i * 12 + p] * L[j * 12 + p];
                L[i * 12 + j] = s2 / dg;
            }
        }
    }
    __syncthreads();
    if (t < N_CLS) {
        double z[12];
        for (int i = 0; i < n; i++) {
            double s = Bm[i * 10 + t];
            for (int p = 0; p < i; p++) s -= L[i * 12 + p] * z[p];
            z[i] = s / L[i * 12 + i];
        }
        for (int i = n - 1; i >= 0; i--) {
            double s = z[i];
            for (int p = i + 1; p < n; p++) s -= L[p * 12 + i] * z[p];
            z[i] = s / L[i * 12 + i];
        }
        for (int i = 0; i < n; i++) {
            d_beta[i * 10 + t] = (float)z[i];
            if (n == MAXK) out[D_IN * MAXK + MAXK + i * 10 + t] = (float)z[i];
        }
    }
}

// y = H[:, :n] @ beta
__global__ void k_yupd(int n) {
    int t = blockIdx.x * blockDim.x + threadIdx.x;
    if (t >= N_ROWS * N_CLS) return;
    int i = t / N_CLS, j = t % N_CLS;
    float s = 0.0f;
    for (int q = 0; q < n; q++) s += d_H[i * MAXK + q] * d_beta[q * 10 + j];
    d_y[t] = s;
}

// ============================================================================
// Launch
// ============================================================================
extern "C" void kernel_launch(void* const* d_in, const int* in_sizes, int n_in,
                              void* d_out, int out_size) {
    const float* X = (const float*)d_in[0];
    const float* Y = (const float*)d_in[1];
    float* out = (float*)d_out;

    k_init<<<1, 32>>>();
    k_zeroy<<<(N_ROWS * N_CLS + 255) / 256, 256>>>();

    int batch = INITB;
    for (int k = 0; k < MAXK; k++) {
        k_keys<<<1, 32>>>();
        for (int r = 0; r < 2; r++) {
            k_zerohist<<<NBUCK / 256, 256>>>();
            k_genhist<<<(N_ROWS + 255) / 256, 256>>>(r);
            k_scan<<<1, 1024>>>();
            k_scatter<<<(N_ROWS + 255) / 256, 256>>>();
            k_bsort<<<NBUCK / 128, 128>>>();
        }
        k_genc<<<(D_IN * NC + NC + 255) / 256, 256>>>();

        int nb = (batch + BM - 1) / BM;
        k_cand<<<nb, 400>>>(X, Y, batch);
        k_vred<<<1, 400>>>(nb);
        k_hc<<<(N_ROWS + 7) / 8, 256>>>(X, out, k);
        k_gram<<<GB, 264>>>(Y, k + 1);
        k_gred<<<1, 288>>>(k + 1);
        k_solve<<<1, 32>>>(out, k + 1);
        k_yupd<<<(N_ROWS * N_CLS + 255) / 256, 256>>>(k + 1);

        batch += BINC;
    }
}